// round 1
// baseline (speedup 1.0000x reference)
#include <cuda_runtime.h>
#include <math.h>

#define B_   8
#define C_   3
#define S_   1024
#define DIM_ 768
#define H_   3
#define HD_  256
#define G_   72          // B*C*H groups
#define OUTW_ (C_*DIM_)  // 2304

// ---- scratch (static __device__ arrays, per harness scratch rules) ----
// 72 * 1024 * 256 floats = 18,874,368 each (75.5 MB x3)
static __device__ float g_Q[18874368];
static __device__ float g_K[18874368];
static __device__ float g_V[18874368];

// ============================================================
// Kernel 1: QKV projection.  Out[s,e] = sum_d X[s,d]*W[e,d] + bias[e]
// Batched over (group g, proj z).  128x128 tile, K-chunk 16, 8x8 micro-tile.
// ============================================================
#define BM 128
#define BN 128
#define BK 16

__global__ __launch_bounds__(256)
void qkv_kernel(const float* __restrict__ x,
                const float* __restrict__ Wq, const float* __restrict__ bq,
                const float* __restrict__ Wk, const float* __restrict__ bk,
                const float* __restrict__ Wv, const float* __restrict__ bv)
{
    __shared__ float As[BK][BM];   // k-major staging (conflict-free compute reads)
    __shared__ float Bs[BK][BN];

    const int tile = blockIdx.x;        // 16 tiles: 8 (M) x 2 (N)
    const int g    = blockIdx.y;        // 72
    const int z    = blockIdx.z;        // 0=Q 1=K 2=V
    const int tm = tile >> 1;
    const int tn = tile & 1;
    const int b = g / (C_ * H_);
    const int c = (g / H_) % C_;
    const int h = g % H_;

    const float* W;  const float* bias;  float* Out;
    if (z == 0)      { W = Wq; bias = bq; Out = g_Q; }
    else if (z == 1) { W = Wk; bias = bk; Out = g_K; }
    else             { W = Wv; bias = bv; Out = g_V; }
    W    += h * HD_ * HD_;
    bias += h * HD_;
    Out  += (size_t)g * S_ * HD_;

    const float* Xg = x + ((size_t)(b * C_ + c) * S_) * DIM_ + h * HD_;

    const int tid = threadIdx.x;
    const int tx = tid & 15;
    const int ty = tid >> 4;

    float acc[8][8];
#pragma unroll
    for (int i = 0; i < 8; i++)
#pragma unroll
        for (int j = 0; j < 8; j++) acc[i][j] = 0.f;

    const int row   = tid >> 1;          // 0..127
    const int cbase = (tid & 1) * 4;     // 0 or 4

    for (int kt = 0; kt < HD_ / BK; kt++) {
        __syncthreads();
        const int k0 = kt * BK;
#pragma unroll
        for (int l = 0; l < 2; l++) {
            const int cc = cbase + l * 8;
            float4 av = *(const float4*)&Xg[(size_t)(tm * BM + row) * DIM_ + k0 + cc];
            As[cc + 0][row] = av.x;  As[cc + 1][row] = av.y;
            As[cc + 2][row] = av.z;  As[cc + 3][row] = av.w;
            float4 wv = *(const float4*)&W[(tn * BN + row) * HD_ + k0 + cc];
            Bs[cc + 0][row] = wv.x;  Bs[cc + 1][row] = wv.y;
            Bs[cc + 2][row] = wv.z;  Bs[cc + 3][row] = wv.w;
        }
        __syncthreads();
#pragma unroll
        for (int k = 0; k < BK; k++) {
            float4 a0 = *(const float4*)&As[k][ty * 8];
            float4 a1 = *(const float4*)&As[k][ty * 8 + 4];
            float4 b0 = *(const float4*)&Bs[k][tx * 8];
            float4 b1 = *(const float4*)&Bs[k][tx * 8 + 4];
            float a[8] = {a0.x, a0.y, a0.z, a0.w, a1.x, a1.y, a1.z, a1.w};
            float bb[8] = {b0.x, b0.y, b0.z, b0.w, b1.x, b1.y, b1.z, b1.w};
#pragma unroll
            for (int i = 0; i < 8; i++)
#pragma unroll
                for (int j = 0; j < 8; j++)
                    acc[i][j] += a[i] * bb[j];
        }
    }

    float bias8[8];
#pragma unroll
    for (int j = 0; j < 8; j++) bias8[j] = bias[tn * BN + tx * 8 + j];

#pragma unroll
    for (int i = 0; i < 8; i++) {
        float4 o0 = make_float4(acc[i][0] + bias8[0], acc[i][1] + bias8[1],
                                acc[i][2] + bias8[2], acc[i][3] + bias8[3]);
        float4 o1 = make_float4(acc[i][4] + bias8[4], acc[i][5] + bias8[5],
                                acc[i][6] + bias8[6], acc[i][7] + bias8[7]);
        float* op = &Out[(size_t)(tm * BM + ty * 8 + i) * HD_ + tn * BN + tx * 8];
        *(float4*)op       = o0;
        *(float4*)(op + 4) = o1;
    }
}

// ============================================================
// Kernel 2: flash attention per (group, 64-query tile).
// Q/K staged d-major (transposed) in smem -> conflict-free LDS.128 for S-GEMM.
// V row-major; O register layout e = u*64 + tx*4 + w (conflict-free V reads).
// ============================================================
#define QT 64
#define KT 64
#define ATTN_SMEM_FLOATS (HD_*QT + HD_*KT + KT*HD_ + QT*KT)   // 53248
#define ATTN_SMEM_BYTES  (ATTN_SMEM_FLOATS * 4)               // 212992

extern __shared__ float smem_attn[];

__global__ __launch_bounds__(256)
void attn_kernel(float* __restrict__ out)
{
    float* Qst = smem_attn;           // [HD_][QT]  d-major, pre-scaled
    float* Kst = Qst + HD_ * QT;      // [HD_][KT]  d-major
    float* Vs  = Kst + HD_ * KT;      // [KT][HD_]  row-major
    float* Ps  = Vs + KT * HD_;       // [QT][KT]

    const int qt = blockIdx.x;        // 16 query tiles
    const int g  = blockIdx.y;        // 72 groups
    const int b = g / (C_ * H_);
    const int c = (g / H_) % C_;
    const int h = g % H_;
    const size_t base = (size_t)g * S_ * HD_;
    const float* Qsrc = g_Q + base + (size_t)qt * QT * HD_;

    const int tid = threadIdx.x;
    const int tx = tid & 15;          // 16 key/col groups
    const int ty = tid >> 4;          // 16 query groups (4 rows each)

    const float scale = 0.0625f;      // 1/sqrt(256)

    // ---- stage Q transposed (d-major) and pre-scaled ----
#pragma unroll
    for (int it = 0; it < 16; it++) {
        const int idx = tid + it * 256;      // float4 index 0..4095
        const int r  = idx & 63;             // query row within tile
        const int c4 = idx >> 6;             // d/4
        float4 v = *(const float4*)&Qsrc[r * HD_ + c4 * 4];
        Qst[(c4 * 4 + 0) * QT + r] = v.x * scale;
        Qst[(c4 * 4 + 1) * QT + r] = v.y * scale;
        Qst[(c4 * 4 + 2) * QT + r] = v.z * scale;
        Qst[(c4 * 4 + 3) * QT + r] = v.w * scale;
    }

    float O[4][16];
    float m[4], l[4];
#pragma unroll
    for (int i = 0; i < 4; i++) {
        m[i] = -1e30f;  l[i] = 0.f;
#pragma unroll
        for (int e = 0; e < 16; e++) O[i][e] = 0.f;
    }

    for (int t = 0; t < S_ / KT; t++) {
        __syncthreads();   // previous tile's PV consumers done (also orders Q staging at t=0)
        const float* Ksrc = g_K + base + (size_t)t * KT * HD_;
        const float* Vsrc = g_V + base + (size_t)t * KT * HD_;
#pragma unroll
        for (int it = 0; it < 16; it++) {
            const int idx = tid + it * 256;
            const int r  = idx & 63;
            const int c4 = idx >> 6;
            float4 v = *(const float4*)&Ksrc[r * HD_ + c4 * 4];
            Kst[(c4 * 4 + 0) * KT + r] = v.x;
            Kst[(c4 * 4 + 1) * KT + r] = v.y;
            Kst[(c4 * 4 + 2) * KT + r] = v.z;
            Kst[(c4 * 4 + 3) * KT + r] = v.w;
            ((float4*)Vs)[idx] = *(const float4*)&Vsrc[idx * 4];
        }
        __syncthreads();

        // ---- S = (Q*scale) . K^T   [4x4 per thread] ----
        float s[4][4];
#pragma unroll
        for (int i = 0; i < 4; i++)
#pragma unroll
            for (int j = 0; j < 4; j++) s[i][j] = 0.f;

#pragma unroll 4
        for (int d = 0; d < HD_; d++) {
            float4 a  = *(const float4*)&Qst[d * QT + ty * 4];
            float4 bb = *(const float4*)&Kst[d * KT + tx * 4];
            float av[4] = {a.x, a.y, a.z, a.w};
            float bv[4] = {bb.x, bb.y, bb.z, bb.w};
#pragma unroll
            for (int i = 0; i < 4; i++)
#pragma unroll
                for (int j = 0; j < 4; j++)
                    s[i][j] += av[i] * bv[j];
        }

        // ---- online softmax ----
#pragma unroll
        for (int i = 0; i < 4; i++) {
            float rm = fmaxf(fmaxf(s[i][0], s[i][1]), fmaxf(s[i][2], s[i][3]));
#pragma unroll
            for (int off = 1; off < 16; off <<= 1)
                rm = fmaxf(rm, __shfl_xor_sync(0xffffffffu, rm, off));
            const float mn = fmaxf(m[i], rm);
            const float alpha = __expf(m[i] - mn);
            float rs = 0.f;
#pragma unroll
            for (int j = 0; j < 4; j++) {
                s[i][j] = __expf(s[i][j] - mn);   // s becomes P
                rs += s[i][j];
            }
#pragma unroll
            for (int off = 1; off < 16; off <<= 1)
                rs += __shfl_xor_sync(0xffffffffu, rs, off);
            l[i] = l[i] * alpha + rs;
            m[i] = mn;
#pragma unroll
            for (int e = 0; e < 16; e++) O[i][e] *= alpha;
            *(float4*)&Ps[(ty * 4 + i) * KT + tx * 4] =
                make_float4(s[i][0], s[i][1], s[i][2], s[i][3]);
        }
        __syncthreads();

        // ---- O += P . V ----
#pragma unroll 4
        for (int j = 0; j < KT; j++) {
            float p0 = Ps[(ty * 4 + 0) * KT + j];
            float p1 = Ps[(ty * 4 + 1) * KT + j];
            float p2 = Ps[(ty * 4 + 2) * KT + j];
            float p3 = Ps[(ty * 4 + 3) * KT + j];
#pragma unroll
            for (int u = 0; u < 4; u++) {
                float4 v = *(const float4*)&Vs[j * HD_ + u * 64 + tx * 4];
                O[0][u * 4 + 0] += p0 * v.x;  O[0][u * 4 + 1] += p0 * v.y;
                O[0][u * 4 + 2] += p0 * v.z;  O[0][u * 4 + 3] += p0 * v.w;
                O[1][u * 4 + 0] += p1 * v.x;  O[1][u * 4 + 1] += p1 * v.y;
                O[1][u * 4 + 2] += p1 * v.z;  O[1][u * 4 + 3] += p1 * v.w;
                O[2][u * 4 + 0] += p2 * v.x;  O[2][u * 4 + 1] += p2 * v.y;
                O[2][u * 4 + 2] += p2 * v.z;  O[2][u * 4 + 3] += p2 * v.w;
                O[3][u * 4 + 0] += p3 * v.x;  O[3][u * 4 + 1] += p3 * v.y;
                O[3][u * 4 + 2] += p3 * v.z;  O[3][u * 4 + 3] += p3 * v.w;
            }
        }
    }

    // ---- finalize: divide by l, write out[b, s, c*768 + h*256 + e] ----
#pragma unroll
    for (int i = 0; i < 4; i++) {
        const float inv = 1.f / l[i];
        const size_t orow = ((size_t)b * S_ + qt * QT + ty * 4 + i) * OUTW_
                          + c * DIM_ + h * HD_;
#pragma unroll
        for (int u = 0; u < 4; u++) {
            float4 o = make_float4(O[i][u * 4 + 0] * inv, O[i][u * 4 + 1] * inv,
                                   O[i][u * 4 + 2] * inv, O[i][u * 4 + 3] * inv);
            *(float4*)&out[orow + u * 64 + tx * 4] = o;
        }
    }
}

// ============================================================
extern "C" void kernel_launch(void* const* d_in, const int* in_sizes, int n_in,
                              void* d_out, int out_size)
{
    const float* x  = (const float*)d_in[0];
    const float* Wq = (const float*)d_in[1];
    const float* bq = (const float*)d_in[2];
    const float* Wk = (const float*)d_in[3];
    const float* bk = (const float*)d_in[4];
    const float* Wv = (const float*)d_in[5];
    const float* bv = (const float*)d_in[6];
    float* out = (float*)d_out;

    cudaFuncSetAttribute(attn_kernel,
                         cudaFuncAttributeMaxDynamicSharedMemorySize,
                         ATTN_SMEM_BYTES);

    qkv_kernel<<<dim3(16, G_, 3), 256>>>(x, Wq, bq, Wk, bk, Wv, bv);
    attn_kernel<<<dim3(S_ / QT, G_), 256, ATTN_SMEM_BYTES>>>(out);
}